// round 14
// baseline (speedup 1.0000x reference)
#include <cuda_runtime.h>
#include <cuda_fp16.h>
#include <cstdint>

// ---------------------------------------------------------------- constants
#define OUT_F   4096
#define IN_F    4096
#define KDIM    4096
#define MROWS   8192
#define NBLOCKS (OUT_F * IN_F / 8)        // 2,097,152

// GEMM tiling (fp16 mma.sync m16n8k16, 2-stage x BK=128 cp.async ring)
#define BM      128
#define BN      256
#define BK      128
#define NITER   (KDIM / BK)               // 32
#define KSTEPS  (BK / 16)                 // 8
#define NTILES  ((MROWS / BM) * (OUT_F / BN))   // 1024
#define GRID_P  152                       // GB300: 152 SMs

#define A_HALF_BYTES  (BM * 128)          // 16 KB
#define B_HALF_BYTES  (BN * 128)          // 32 KB
#define B_BASE_OFF    (2 * A_HALF_BYTES)  // 32 KB
#define STAGE_BYTES   (2 * A_HALF_BYTES + 2 * B_HALF_BYTES)   // 96 KB
#define SMEM_TOTAL    (2 * STAGE_BYTES)                       // 192 KB

// merged pre-pass grid: every 5th CTA reconstructs W, the rest convert X
#define REC_CTAS   4096
#define CVT_CTAS   16384
#define PRE_GRID   (REC_CTAS + CVT_CTAS)  // 20480

__device__ __half g_Wh[(size_t)OUT_F * IN_F];   // 34 MB
__device__ __half g_Xh[(size_t)MROWS * KDIM];   // 67 MB
__device__ unsigned int g_tile_ctr;             // work-stealing cursor

// ---------------------------------------------------------------- helpers
__device__ __forceinline__ uint32_t smem_u32(const void* p) {
    uint32_t a;
    asm("{ .reg .u64 t; cvta.to.shared.u64 t, %1; cvt.u32.u64 %0, t; }"
        : "=r"(a) : "l"(p));
    return a;
}

#define CP_ASYNC16(sm, gp) \
    asm volatile("cp.async.cg.shared.global [%0], [%1], 16;" :: "r"(sm), "l"(gp) : "memory")
#define CP_COMMIT() asm volatile("cp.async.commit_group;" ::: "memory")
#define CP_WAIT(n)  asm volatile("cp.async.wait_group %0;" :: "n"(n) : "memory")

#define LDMATRIX_X4(r, a) \
    asm volatile("ldmatrix.sync.aligned.m8n8.x4.shared.b16 {%0,%1,%2,%3}, [%4];" \
                 : "=r"((r)[0]), "=r"((r)[1]), "=r"((r)[2]), "=r"((r)[3]) : "r"(a))

__device__ __forceinline__ void mma_f16(float* c, const uint32_t* a, const uint32_t* b) {
    asm volatile(
        "mma.sync.aligned.m16n8k16.row.col.f32.f16.f16.f32 "
        "{%0,%1,%2,%3}, {%4,%5,%6,%7}, {%8,%9}, {%0,%1,%2,%3};"
        : "+f"(c[0]), "+f"(c[1]), "+f"(c[2]), "+f"(c[3])
        : "r"(a[0]), "r"(a[1]), "r"(a[2]), "r"(a[3]),
          "r"(b[0]), "r"(b[1]));
}

// ---------------------------------------------------------------- merged pre-pass
__global__ void k_prepass(const float4* __restrict__ x,
                          const void* __restrict__ indices,
                          const float* __restrict__ cb) {
    const int bid = blockIdx.x;
    if (bid == 0 && threadIdx.x == 0) g_tile_ctr = GRID_P;   // reset per replay
    const int q = bid / 5, rm = bid - q * 5;

    if (rm == 4) {
        // ---- reconstruct: 512 codebook blocks, 2 per thread
        const long long B0 = (long long)q * 512;
        __shared__ int s_is32;
        if (threadIdx.x == 0) s_is32 = 0;
        __syncthreads();
        if (threadIdx.x < 32) {
            // odd 32-bit words of an int64 buffer here are hi-halves of
            // values < 4096 => all zero. int32 random indices: ~never.
            long long w = (B0 + 2 * threadIdx.x) | 1;
            if (((const int*)indices)[w] != 0) s_is32 = 1;
        }
        __syncthreads();
        const bool is32 = s_is32 != 0;

        long long b = B0 + threadIdx.x * 2;
        long long v0, v1;
        if (is32) {
            v0 = ((const int*)indices)[b];
            v1 = ((const int*)indices)[b + 1];
        } else {
            v0 = ((const long long*)indices)[b];
            v1 = ((const long long*)indices)[b + 1];
        }
        const float4* s0 = (const float4*)(cb + v0 * 8);
        const float4* s1 = (const float4*)(cb + v1 * 8);
        float4 a0 = s0[0], a1 = s0[1], c0 = s1[0], c1 = s1[1];
        __half2 h[8];
        h[0] = __floats2half2_rn(a0.x, a0.y);
        h[1] = __floats2half2_rn(a0.z, a0.w);
        h[2] = __floats2half2_rn(a1.x, a1.y);
        h[3] = __floats2half2_rn(a1.z, a1.w);
        h[4] = __floats2half2_rn(c0.x, c0.y);
        h[5] = __floats2half2_rn(c0.z, c0.w);
        h[6] = __floats2half2_rn(c1.x, c1.y);
        h[7] = __floats2half2_rn(c1.z, c1.w);
        uint4* dst = (uint4*)(g_Wh + b * 8);
        dst[0] = ((uint4*)h)[0];
        dst[1] = ((uint4*)h)[1];
    } else {
        // ---- convert: 2048 floats per CTA, 8 per thread
        const size_t t = (size_t)q * 4 + rm;
        const size_t i = t * 256 + threadIdx.x;
        float4 a = x[2 * i], b = x[2 * i + 1];
        __half2 h[4];
        h[0] = __floats2half2_rn(a.x, a.y);
        h[1] = __floats2half2_rn(a.z, a.w);
        h[2] = __floats2half2_rn(b.x, b.y);
        h[3] = __floats2half2_rn(b.z, b.w);
        *(uint4*)(g_Xh + i * 8) = *(uint4*)h;
    }
}

// ---------------------------------------------------------------- GEMM
__global__ __launch_bounds__(256, 1)
void k_gemm(const float* __restrict__ bias, float* __restrict__ C) {
    extern __shared__ char smem[];
    const uint32_t smem_b = smem_u32(smem);
    __shared__ unsigned int s_next;

    const int tid  = threadIdx.x;
    const int lane = tid & 31;
    const int wid  = tid >> 5;
    const int gid  = lane >> 2;
    const int tg   = lane & 3;
    const int wm   = wid & 1;
    const int wn   = wid >> 1;

    // ---- tile-independent smem fill offsets
    uint32_t sA[4], sB[8];
    #pragma unroll
    for (int i = 0; i < 4; i++) {
        int v = tid + i * 256, r = v >> 3, ch = v & 7;
        sA[i] = (uint32_t)(r * 128 + ((ch ^ (r & 7)) << 4));
    }
    #pragma unroll
    for (int i = 0; i < 8; i++) {
        int v = tid + i * 256, r = v >> 3, ch = v & 7;
        sB[i] = (uint32_t)(B_BASE_OFF + r * 128 + ((ch ^ (r & 7)) << 4));
    }

    // ---- tile-dependent global bases
    const __half* gA[4];
    const __half* gB[8];
    auto set_tables = [&](int t) {
        const int tm0 = (t >> 4) * BM, tn0 = (t & 15) * BN;
        #pragma unroll
        for (int i = 0; i < 4; i++) {
            int v = tid + i * 256, r = v >> 3, ch = v & 7;
            gA[i] = g_Xh + (size_t)(tm0 + r) * KDIM + ch * 8;
        }
        #pragma unroll
        for (int i = 0; i < 8; i++) {
            int v = tid + i * 256, r = v >> 3, ch = v & 7;
            gB[i] = g_Wh + (size_t)(tn0 + r) * KDIM + ch * 8;
        }
    };

    auto fill_op = [&](uint32_t sbase, int o, int kt) {
        if (o < 8) {
            const int i = o & 3, kh = o >> 2;
            CP_ASYNC16(sbase + kh * A_HALF_BYTES + sA[i], gA[i] + kt + kh * 64);
        } else {
            const int i = (o - 8) & 7, kh = (o - 8) >> 3;
            CP_ASYNC16(sbase + kh * B_HALF_BYTES + sB[i], gB[i] + kt + kh * 64);
        }
    };

    // ---- ldmatrix per-lane bases
    const int row_off = lane & 7;
    const int a_kb = lane >> 4;
    const int b_kb = (lane >> 3) & 1;
    uint32_t aoff[4], boff[4];
    #pragma unroll
    for (int mf = 0; mf < 4; mf++)
        aoff[mf] = (uint32_t)((wm * 64 + mf * 16 + row_off + ((lane >> 3) & 1) * 8) * 128);
    #pragma unroll
    for (int p = 0; p < 4; p++)
        boff[p] = (uint32_t)((wn * 64 + p * 16 + ((lane >> 4) & 1) * 8 + row_off) * 128);

    float acc[4][8][4];
    #pragma unroll
    for (int mf = 0; mf < 4; mf++)
        #pragma unroll
        for (int nf = 0; nf < 8; nf++)
            #pragma unroll
            for (int r = 0; r < 4; r++) acc[mf][nf][r] = 0.f;

    uint32_t a_frag[2][4][4];
    uint32_t b_frag[2][4][4];

    // iteration body: consume `stage`, fill `nstage` (knext) if do_fill
    auto body = [&](uint32_t stage, uint32_t nstage, int knext, bool do_fill) {
        {   // preload ks=0 fragments, interleaved
            const uint32_t ac = (uint32_t)((a_kb ^ row_off) << 4);
            const uint32_t bc = (uint32_t)((b_kb ^ row_off) << 4);
            LDMATRIX_X4(a_frag[0][0], stage + aoff[0] + ac);
            LDMATRIX_X4(b_frag[0][0], stage + B_BASE_OFF + boff[0] + bc);
            LDMATRIX_X4(a_frag[0][1], stage + aoff[1] + ac);
            LDMATRIX_X4(b_frag[0][1], stage + B_BASE_OFF + boff[1] + bc);
            LDMATRIX_X4(a_frag[0][2], stage + aoff[2] + ac);
            LDMATRIX_X4(b_frag[0][2], stage + B_BASE_OFF + boff[2] + bc);
            LDMATRIX_X4(a_frag[0][3], stage + aoff[3] + ac);
            LDMATRIX_X4(b_frag[0][3], stage + B_BASE_OFF + boff[3] + bc);
        }
        #pragma unroll
        for (int ks = 0; ks < KSTEPS; ks++) {
            const int cur = ks & 1;
            if (do_fill && ks < 4) {
                #pragma unroll
                for (int j = 0; j < 6; j++)
                    fill_op(nstage, ks * 6 + j, knext);
                if (ks == 3) CP_COMMIT();
            }
            if (ks + 1 < KSTEPS) {
                const int nb  = cur ^ 1;
                const int kn  = ks + 1;
                const int kh  = kn >> 2;
                const int kk  = kn & 3;
                const uint32_t abase = stage + kh * A_HALF_BYTES;
                const uint32_t bbase = stage + B_BASE_OFF + kh * B_HALF_BYTES;
                const uint32_t ac = (uint32_t)((((2 * kk) | a_kb) ^ row_off) << 4);
                const uint32_t bc = (uint32_t)((((2 * kk) | b_kb) ^ row_off) << 4);
                #pragma unroll
                for (int mf = 0; mf < 4; mf++) LDMATRIX_X4(a_frag[nb][mf], abase + aoff[mf] + ac);
                #pragma unroll
                for (int p = 0; p < 4; p++)    LDMATRIX_X4(b_frag[nb][p],  bbase + boff[p]  + bc);
            }
            #pragma unroll
            for (int mf = 0; mf < 4; mf++)
                #pragma unroll
                for (int p = 0; p < 4; p++) {
                    mma_f16(acc[mf][2 * p],     a_frag[cur][mf], &b_frag[cur][p][0]);
                    mma_f16(acc[mf][2 * p + 1], a_frag[cur][mf], &b_frag[cur][p][2]);
                }
        }
        if (!do_fill) CP_COMMIT();   // balance group accounting
    };

    // ---- persistent tile loop (atomic work stealing)
    int tile = blockIdx.x;
    set_tables(tile);
    #pragma unroll
    for (int o = 0; o < 24; o++) fill_op(smem_b, o, 0);
    CP_COMMIT();

    while (tile < NTILES) {
        const int m0 = (tile >> 4) * BM;
        const int n0 = (tile & 15) * BN;

        // bias prefetch (overlaps in-flight stage-0 fill)
        const int nbase = n0 + wn * 64;
        float bv[8][2];
        #pragma unroll
        for (int nf = 0; nf < 8; nf++) {
            const int cc = nbase + nf * 8 + 2 * tg;
            bv[nf][0] = __ldg(bias + cc);
            bv[nf][1] = __ldg(bias + cc + 1);
        }

        // iterations 0..NITER-2 (current-tile fills)
        for (int it = 0; it < NITER - 1; it++) {
            const int s = it & 1;
            CP_WAIT(0);
            __syncthreads();
            // grab next tile once; this barrier guarantees every thread already
            // consumed the previous s_next value
            if (it == 0 && tid == 0) s_next = atomicAdd(&g_tile_ctr, 1u);
            body(smem_b + s * STAGE_BYTES, smem_b + (s ^ 1) * STAGE_BYTES,
                 (it + 1) * BK, true);
        }

        // peeled last iteration: consume stage 1, fill next tile's k=0 into stage 0
        CP_WAIT(0);
        __syncthreads();
        const int next_tile = (int)s_next;
        const bool df = next_tile < NTILES;
        if (df) set_tables(next_tile);
        body(smem_b + STAGE_BYTES, smem_b, 0, df);

        // epilogue (overlaps next tile's in-flight fill) + acc reset
        const int mbase = m0 + wm * 64;
        #pragma unroll
        for (int nf = 0; nf < 8; nf++) {
            const int cc = nbase + nf * 8 + 2 * tg;
            #pragma unroll
            for (int mf = 0; mf < 4; mf++) {
                const int r = mbase + mf * 16 + gid;
                float2 v0 = make_float2(acc[mf][nf][0] + bv[nf][0], acc[mf][nf][1] + bv[nf][1]);
                float2 v1 = make_float2(acc[mf][nf][2] + bv[nf][0], acc[mf][nf][3] + bv[nf][1]);
                *(float2*)(C + (size_t)r * OUT_F + cc)       = v0;
                *(float2*)(C + (size_t)(r + 8) * OUT_F + cc) = v1;
                acc[mf][nf][0] = 0.f; acc[mf][nf][1] = 0.f;
                acc[mf][nf][2] = 0.f; acc[mf][nf][3] = 0.f;
            }
        }
        tile = next_tile;
    }
}

// ---------------------------------------------------------------- launch
extern "C" void kernel_launch(void* const* d_in, const int* in_sizes, int n_in,
                              void* d_out, int out_size) {
    const float* x    = (const float*)d_in[0];   // [4,2048,4096]
    const float* cb   = (const float*)d_in[1];   // [4096,8]
    const void*  idx  = d_in[2];                 // [NBLOCKS] int32 or int64
    const float* bias = (const float*)d_in[3];   // [4096]
    float* out = (float*)d_out;

    k_prepass<<<PRE_GRID, 256>>>((const float4*)x, idx, cb);

    cudaFuncSetAttribute(k_gemm, cudaFuncAttributeMaxDynamicSharedMemorySize, SMEM_TOTAL);
    k_gemm<<<GRID_P, 256, SMEM_TOTAL>>>(bias, out);
}

// round 15
// speedup vs baseline: 1.0089x; 1.0089x over previous
#include <cuda_runtime.h>
#include <cuda_fp16.h>
#include <cstdint>

// ---------------------------------------------------------------- constants
#define OUT_F   4096
#define IN_F    4096
#define KDIM    4096
#define MROWS   8192
#define NBLOCKS (OUT_F * IN_F / 8)        // 2,097,152

// GEMM tiling (fp16 mma.sync m16n8k16, 2-stage x BK=128 cp.async ring)
#define BM      128
#define BN      256
#define BK      128
#define NITER   (KDIM / BK)               // 32
#define KSTEPS  (BK / 16)                 // 8

#define A_HALF_BYTES  (BM * 128)          // 16 KB
#define B_HALF_BYTES  (BN * 128)          // 32 KB
#define B_BASE_OFF    (2 * A_HALF_BYTES)  // 32 KB
#define STAGE_BYTES   (2 * A_HALF_BYTES + 2 * B_HALF_BYTES)   // 96 KB
#define SMEM_TOTAL    (2 * STAGE_BYTES)                       // 192 KB

// merged pre-pass grid: every 5th CTA reconstructs W, the rest convert X
#define REC_CTAS   4096
#define CVT_CTAS   16384
#define PRE_GRID   (REC_CTAS + CVT_CTAS)  // 20480

__device__ __half g_Wh[(size_t)OUT_F * IN_F];   // 34 MB
__device__ __half g_Xh[(size_t)MROWS * KDIM];   // 67 MB

// ---------------------------------------------------------------- helpers
__device__ __forceinline__ uint32_t smem_u32(const void* p) {
    uint32_t a;
    asm("{ .reg .u64 t; cvta.to.shared.u64 t, %1; cvt.u32.u64 %0, t; }"
        : "=r"(a) : "l"(p));
    return a;
}

#define CP_ASYNC16(sm, gp) \
    asm volatile("cp.async.cg.shared.global [%0], [%1], 16;" :: "r"(sm), "l"(gp) : "memory")
#define CP_COMMIT() asm volatile("cp.async.commit_group;" ::: "memory")
#define CP_WAIT(n)  asm volatile("cp.async.wait_group %0;" :: "n"(n) : "memory")

#define LDMATRIX_X4(r, a) \
    asm volatile("ldmatrix.sync.aligned.m8n8.x4.shared.b16 {%0,%1,%2,%3}, [%4];" \
                 : "=r"((r)[0]), "=r"((r)[1]), "=r"((r)[2]), "=r"((r)[3]) : "r"(a))

__device__ __forceinline__ void mma_f16(float* c, const uint32_t* a, const uint32_t* b) {
    asm volatile(
        "mma.sync.aligned.m16n8k16.row.col.f32.f16.f16.f32 "
        "{%0,%1,%2,%3}, {%4,%5,%6,%7}, {%8,%9}, {%0,%1,%2,%3};"
        : "+f"(c[0]), "+f"(c[1]), "+f"(c[2]), "+f"(c[3])
        : "r"(a[0]), "r"(a[1]), "r"(a[2]), "r"(a[3]),
          "r"(b[0]), "r"(b[1]));
}

// ---------------------------------------------------------------- merged pre-pass
__global__ void k_prepass(const float4* __restrict__ x,
                          const void* __restrict__ indices,
                          const float* __restrict__ cb) {
    const int bid = blockIdx.x;
    const int q = bid / 5, rm = bid - q * 5;

    if (rm == 4) {
        // ---- reconstruct: 512 codebook blocks, 2 per thread
        const long long B0 = (long long)q * 512;
        __shared__ int s_is32;
        if (threadIdx.x == 0) s_is32 = 0;
        __syncthreads();
        if (threadIdx.x < 32) {
            // odd 32-bit words of an int64 buffer here are hi-halves of
            // values < 4096 => all zero. int32 random indices: ~never.
            long long w = (B0 + 2 * threadIdx.x) | 1;
            if (((const int*)indices)[w] != 0) s_is32 = 1;
        }
        __syncthreads();
        const bool is32 = s_is32 != 0;

        long long b = B0 + threadIdx.x * 2;
        long long v0, v1;
        if (is32) {
            v0 = ((const int*)indices)[b];
            v1 = ((const int*)indices)[b + 1];
        } else {
            v0 = ((const long long*)indices)[b];
            v1 = ((const long long*)indices)[b + 1];
        }
        const float4* s0 = (const float4*)(cb + v0 * 8);
        const float4* s1 = (const float4*)(cb + v1 * 8);
        float4 a0 = s0[0], a1 = s0[1], c0 = s1[0], c1 = s1[1];
        __half2 h[8];
        h[0] = __floats2half2_rn(a0.x, a0.y);
        h[1] = __floats2half2_rn(a0.z, a0.w);
        h[2] = __floats2half2_rn(a1.x, a1.y);
        h[3] = __floats2half2_rn(a1.z, a1.w);
        h[4] = __floats2half2_rn(c0.x, c0.y);
        h[5] = __floats2half2_rn(c0.z, c0.w);
        h[6] = __floats2half2_rn(c1.x, c1.y);
        h[7] = __floats2half2_rn(c1.z, c1.w);
        uint4* dst = (uint4*)(g_Wh + b * 8);
        dst[0] = ((uint4*)h)[0];
        dst[1] = ((uint4*)h)[1];
    } else {
        // ---- convert: 2048 floats per CTA, 8 per thread
        const size_t t = (size_t)q * 4 + rm;
        const size_t i = t * 256 + threadIdx.x;
        float4 a = x[2 * i], b = x[2 * i + 1];
        __half2 h[4];
        h[0] = __floats2half2_rn(a.x, a.y);
        h[1] = __floats2half2_rn(a.z, a.w);
        h[2] = __floats2half2_rn(b.x, b.y);
        h[3] = __floats2half2_rn(b.z, b.w);
        *(uint4*)(g_Xh + i * 8) = *(uint4*)h;
    }
}

// ---------------------------------------------------------------- GEMM
__global__ __launch_bounds__(256, 1)
void k_gemm(const float* __restrict__ bias, float* __restrict__ C) {
    extern __shared__ char smem[];
    const uint32_t smem_b = smem_u32(smem);

    const int tid  = threadIdx.x;
    const int lane = tid & 31;
    const int wid  = tid >> 5;
    const int gid  = lane >> 2;
    const int tg   = lane & 3;
    const int wm   = wid & 1;
    const int wn   = wid >> 1;

    const int m0 = blockIdx.y * BM;
    const int n0 = blockIdx.x * BN;

    // ---- compact fill tables: 12 base ptrs + 12 base smem offsets.
    uint32_t sA[4], sB[8];
    const __half* gA[4];
    const __half* gB[8];
    #pragma unroll
    for (int i = 0; i < 4; i++) {
        int v = tid + i * 256, r = v >> 3, ch = v & 7;
        sA[i] = (uint32_t)(r * 128 + ((ch ^ (r & 7)) << 4));
        gA[i] = g_Xh + (size_t)(m0 + r) * KDIM + ch * 8;
    }
    #pragma unroll
    for (int i = 0; i < 8; i++) {
        int v = tid + i * 256, r = v >> 3, ch = v & 7;
        sB[i] = (uint32_t)(B_BASE_OFF + r * 128 + ((ch ^ (r & 7)) << 4));
        gB[i] = g_Wh + (size_t)(n0 + r) * KDIM + ch * 8;
    }

    // one fill op, o = compile-time constant in unrolled loops
    auto fill_op = [&](uint32_t sbase, int o, int kt) {
        if (o < 8) {
            const int i = o & 3, kh = o >> 2;
            CP_ASYNC16(sbase + kh * A_HALF_BYTES + sA[i], gA[i] + kt + kh * 64);
        } else {
            const int i = (o - 8) & 7, kh = (o - 8) >> 3;
            CP_ASYNC16(sbase + kh * B_HALF_BYTES + sB[i], gB[i] + kt + kh * 64);
        }
    };

    // ---- ldmatrix per-lane bases
    const int row_off = lane & 7;
    const int a_kb = lane >> 4;
    const int b_kb = (lane >> 3) & 1;
    uint32_t aoff[4], boff[4];
    #pragma unroll
    for (int mf = 0; mf < 4; mf++)
        aoff[mf] = (uint32_t)((wm * 64 + mf * 16 + row_off + ((lane >> 3) & 1) * 8) * 128);
    #pragma unroll
    for (int p = 0; p < 4; p++)
        boff[p] = (uint32_t)((wn * 64 + p * 16 + ((lane >> 4) & 1) * 8 + row_off) * 128);

    // ---- prefill stage 0
    #pragma unroll
    for (int o = 0; o < 24; o++) fill_op(smem_b, o, 0);
    CP_COMMIT();

    // ---- prefetch bias into registers (overlaps prologue fill latency)
    const int nbase = n0 + wn * 64;
    float bv[8][2];
    #pragma unroll
    for (int nf = 0; nf < 8; nf++) {
        const int cc = nbase + nf * 8 + 2 * tg;
        bv[nf][0] = __ldg(bias + cc);
        bv[nf][1] = __ldg(bias + cc + 1);
    }

    float acc[4][8][4];
    #pragma unroll
    for (int mf = 0; mf < 4; mf++)
        #pragma unroll
        for (int nf = 0; nf < 8; nf++)
            #pragma unroll
            for (int r = 0; r < 4; r++) acc[mf][nf][r] = 0.f;

    uint32_t a_frag[2][4][4];
    uint32_t b_frag[2][4][4];

    for (int it = 0; it < NITER; it++) {
        const int s = it & 1;
        const uint32_t stage = smem_b + s * STAGE_BYTES;
        const uint32_t nstage = smem_b + (s ^ 1) * STAGE_BYTES;
        const int knext = (it + 1) * BK;
        const bool do_fill = (it + 1 < NITER);

        CP_WAIT(0);
        __syncthreads();

        // preload ks=0 fragments, interleaved so first MMA's deps land first
        {
            const uint32_t ac = (uint32_t)((a_kb ^ row_off) << 4);
            const uint32_t bc = (uint32_t)((b_kb ^ row_off) << 4);
            LDMATRIX_X4(a_frag[0][0], stage + aoff[0] + ac);
            LDMATRIX_X4(b_frag[0][0], stage + B_BASE_OFF + boff[0] + bc);
            LDMATRIX_X4(a_frag[0][1], stage + aoff[1] + ac);
            LDMATRIX_X4(b_frag[0][1], stage + B_BASE_OFF + boff[1] + bc);
            LDMATRIX_X4(a_frag[0][2], stage + aoff[2] + ac);
            LDMATRIX_X4(b_frag[0][2], stage + B_BASE_OFF + boff[2] + bc);
            LDMATRIX_X4(a_frag[0][3], stage + aoff[3] + ac);
            LDMATRIX_X4(b_frag[0][3], stage + B_BASE_OFF + boff[3] + bc);
        }

        #pragma unroll
        for (int ks = 0; ks < KSTEPS; ks++) {
            const int cur = ks & 1;
            // fill 8 ops/k-step over ks=0..2; commit at ks==2 =>
            // group ages ~5 k-steps (~1600 cyc) before the next wait
            if (do_fill && ks < 3) {
                #pragma unroll
                for (int j = 0; j < 8; j++)
                    fill_op(nstage, ks * 8 + j, knext);
                if (ks == 2) CP_COMMIT();
            }
            if (ks + 1 < KSTEPS) {
                const int nb  = cur ^ 1;
                const int kn  = ks + 1;
                const int kh  = kn >> 2;
                const int kk  = kn & 3;
                const uint32_t abase = stage + kh * A_HALF_BYTES;
                const uint32_t bbase = stage + B_BASE_OFF + kh * B_HALF_BYTES;
                const uint32_t ac = (uint32_t)((((2 * kk) | a_kb) ^ row_off) << 4);
                const uint32_t bc = (uint32_t)((((2 * kk) | b_kb) ^ row_off) << 4);
                #pragma unroll
                for (int mf = 0; mf < 4; mf++) LDMATRIX_X4(a_frag[nb][mf], abase + aoff[mf] + ac);
                #pragma unroll
                for (int p = 0; p < 4; p++)    LDMATRIX_X4(b_frag[nb][p],  bbase + boff[p]  + bc);
            }
            #pragma unroll
            for (int mf = 0; mf < 4; mf++)
                #pragma unroll
                for (int p = 0; p < 4; p++) {
                    mma_f16(acc[mf][2 * p],     a_frag[cur][mf], &b_frag[cur][p][0]);
                    mma_f16(acc[mf][2 * p + 1], a_frag[cur][mf], &b_frag[cur][p][2]);
                }
        }
        if (!do_fill) CP_COMMIT();   // balance group accounting on last iter
    }

    // ---- epilogue: bias + store (bias already in registers)
    const int mbase = m0 + wm * 64;
    #pragma unroll
    for (int nf = 0; nf < 8; nf++) {
        const int cc = nbase + nf * 8 + 2 * tg;
        #pragma unroll
        for (int mf = 0; mf < 4; mf++) {
            const int r = mbase + mf * 16 + gid;
            float2 v0 = make_float2(acc[mf][nf][0] + bv[nf][0], acc[mf][nf][1] + bv[nf][1]);
            float2 v1 = make_float2(acc[mf][nf][2] + bv[nf][0], acc[mf][nf][3] + bv[nf][1]);
            *(float2*)(C + (size_t)r * OUT_F + cc)       = v0;
            *(float2*)(C + (size_t)(r + 8) * OUT_F + cc) = v1;
        }
    }
}

// ---------------------------------------------------------------- launch
extern "C" void kernel_launch(void* const* d_in, const int* in_sizes, int n_in,
                              void* d_out, int out_size) {
    const float* x    = (const float*)d_in[0];   // [4,2048,4096]
    const float* cb   = (const float*)d_in[1];   // [4096,8]
    const void*  idx  = d_in[2];                 // [NBLOCKS] int32 or int64
    const float* bias = (const float*)d_in[3];   // [4096]
    float* out = (float*)d_out;

    k_prepass<<<PRE_GRID, 256>>>((const float4*)x, idx, cb);

    cudaFuncSetAttribute(k_gemm, cudaFuncAttributeMaxDynamicSharedMemorySize, SMEM_TOTAL);
    dim3 grid(OUT_F / BN, MROWS / BM);   // (16, 64)
    k_gemm<<<grid, 256, SMEM_TOTAL>>>(bias, out);
}

// round 17
// speedup vs baseline: 1.0171x; 1.0082x over previous
#include <cuda_runtime.h>
#include <cuda_fp16.h>
#include <cstdint>

// ---------------------------------------------------------------- constants
#define OUT_F   4096
#define IN_F    4096
#define KDIM    4096
#define MROWS   8192
#define NBLOCKS (OUT_F * IN_F / 8)        // 2,097,152

// GEMM tiling (fp16 mma.sync m16n8k16, 2-stage x BK=128 cp.async ring)
#define BM      128
#define BN      256
#define BK      128
#define NITER   (KDIM / BK)               // 32
#define KSTEPS  (BK / 16)                 // 8

#define A_HALF_BYTES  (BM * 128)          // 16 KB
#define B_HALF_BYTES  (BN * 128)          // 32 KB
#define B_BASE_OFF    (2 * A_HALF_BYTES)  // 32 KB
#define STAGE_BYTES   (2 * A_HALF_BYTES + 2 * B_HALF_BYTES)   // 96 KB
#define SMEM_TOTAL    (2 * STAGE_BYTES)                       // 192 KB

// merged pre-pass grid: every 5th CTA reconstructs W, the rest convert X
#define REC_CTAS   4096
#define CVT_CTAS   16384
#define PRE_GRID   (REC_CTAS + CVT_CTAS)  // 20480

__device__ __half g_Wh[(size_t)OUT_F * IN_F];   // 34 MB
__device__ __half g_Xh[(size_t)MROWS * KDIM];   // 67 MB

// ---------------------------------------------------------------- helpers
__device__ __forceinline__ uint32_t smem_u32(const void* p) {
    uint32_t a;
    asm("{ .reg .u64 t; cvta.to.shared.u64 t, %1; cvt.u32.u64 %0, t; }"
        : "=r"(a) : "l"(p));
    return a;
}

#define CP_ASYNC16(sm, gp) \
    asm volatile("cp.async.cg.shared.global [%0], [%1], 16;" :: "r"(sm), "l"(gp) : "memory")
#define CP_COMMIT() asm volatile("cp.async.commit_group;" ::: "memory")
#define CP_WAIT(n)  asm volatile("cp.async.wait_group %0;" :: "n"(n) : "memory")

#define LDMATRIX_X4(r, a) \
    asm volatile("ldmatrix.sync.aligned.m8n8.x4.shared.b16 {%0,%1,%2,%3}, [%4];" \
                 : "=r"((r)[0]), "=r"((r)[1]), "=r"((r)[2]), "=r"((r)[3]) : "r"(a))

__device__ __forceinline__ void mma_f16(float* c, const uint32_t* a, const uint32_t* b) {
    asm volatile(
        "mma.sync.aligned.m16n8k16.row.col.f32.f16.f16.f32 "
        "{%0,%1,%2,%3}, {%4,%5,%6,%7}, {%8,%9}, {%0,%1,%2,%3};"
        : "+f"(c[0]), "+f"(c[1]), "+f"(c[2]), "+f"(c[3])
        : "r"(a[0]), "r"(a[1]), "r"(a[2]), "r"(a[3]),
          "r"(b[0]), "r"(b[1]));
}

// ---------------------------------------------------------------- merged pre-pass
__global__ void k_prepass(const float4* __restrict__ x,
                          const void* __restrict__ indices,
                          const float* __restrict__ cb) {
    const int bid = blockIdx.x;
    const int q = bid / 5, rm = bid - q * 5;

    if (rm == 4) {
        // ---- reconstruct: 512 codebook blocks, 2 per thread
        const long long B0 = (long long)q * 512;
        __shared__ int s_is32;
        if (threadIdx.x == 0) s_is32 = 0;
        __syncthreads();
        if (threadIdx.x < 32) {
            // odd 32-bit words of an int64 buffer here are hi-halves of
            // values < 4096 => all zero. int32 random indices: ~never.
            long long w = (B0 + 2 * threadIdx.x) | 1;
            if (((const int*)indices)[w] != 0) s_is32 = 1;
        }
        __syncthreads();
        const bool is32 = s_is32 != 0;

        long long b = B0 + threadIdx.x * 2;
        long long v0, v1;
        if (is32) {
            v0 = ((const int*)indices)[b];
            v1 = ((const int*)indices)[b + 1];
        } else {
            v0 = ((const long long*)indices)[b];
            v1 = ((const long long*)indices)[b + 1];
        }
        const float4* s0 = (const float4*)(cb + v0 * 8);
        const float4* s1 = (const float4*)(cb + v1 * 8);
        float4 a0 = s0[0], a1 = s0[1], c0 = s1[0], c1 = s1[1];
        __half2 h[8];
        h[0] = __floats2half2_rn(a0.x, a0.y);
        h[1] = __floats2half2_rn(a0.z, a0.w);
        h[2] = __floats2half2_rn(a1.x, a1.y);
        h[3] = __floats2half2_rn(a1.z, a1.w);
        h[4] = __floats2half2_rn(c0.x, c0.y);
        h[5] = __floats2half2_rn(c0.z, c0.w);
        h[6] = __floats2half2_rn(c1.x, c1.y);
        h[7] = __floats2half2_rn(c1.z, c1.w);
        uint4* dst = (uint4*)(g_Wh + b * 8);
        dst[0] = ((uint4*)h)[0];
        dst[1] = ((uint4*)h)[1];
    } else {
        // ---- convert: 2048 floats per CTA, 8 per thread
        const size_t t = (size_t)q * 4 + rm;
        const size_t i = t * 256 + threadIdx.x;
        float4 a = x[2 * i], b = x[2 * i + 1];
        __half2 h[4];
        h[0] = __floats2half2_rn(a.x, a.y);
        h[1] = __floats2half2_rn(a.z, a.w);
        h[2] = __floats2half2_rn(b.x, b.y);
        h[3] = __floats2half2_rn(b.z, b.w);
        *(uint4*)(g_Xh + i * 8) = *(uint4*)h;
    }
    // allow the dependent GEMM to launch and run its prologue while this
    // grid drains; our global stores above precede the trigger.
    asm volatile("griddepcontrol.launch_dependents;");
}

// ---------------------------------------------------------------- GEMM
__global__ __launch_bounds__(256, 1)
void k_gemm(const float* __restrict__ bias, float* __restrict__ C) {
    extern __shared__ char smem[];
    const uint32_t smem_b = smem_u32(smem);

    const int tid  = threadIdx.x;
    const int lane = tid & 31;
    const int wid  = tid >> 5;
    const int gid  = lane >> 2;
    const int tg   = lane & 3;
    const int wm   = wid & 1;
    const int wn   = wid >> 1;

    const int m0 = blockIdx.y * BM;
    const int n0 = blockIdx.x * BN;

    // ---- compact fill tables: 12 base ptrs + 12 base smem offsets.
    uint32_t sA[4], sB[8];
    const __half* gA[4];
    const __half* gB[8];
    #pragma unroll
    for (int i = 0; i < 4; i++) {
        int v = tid + i * 256, r = v >> 3, ch = v & 7;
        sA[i] = (uint32_t)(r * 128 + ((ch ^ (r & 7)) << 4));
        gA[i] = g_Xh + (size_t)(m0 + r) * KDIM + ch * 8;
    }
    #pragma unroll
    for (int i = 0; i < 8; i++) {
        int v = tid + i * 256, r = v >> 3, ch = v & 7;
        sB[i] = (uint32_t)(B_BASE_OFF + r * 128 + ((ch ^ (r & 7)) << 4));
        gB[i] = g_Wh + (size_t)(n0 + r) * KDIM + ch * 8;
    }

    // one fill op, o = compile-time constant in unrolled loops
    auto fill_op = [&](uint32_t sbase, int o, int kt) {
        if (o < 8) {
            const int i = o & 3, kh = o >> 2;
            CP_ASYNC16(sbase + kh * A_HALF_BYTES + sA[i], gA[i] + kt + kh * 64);
        } else {
            const int i = (o - 8) & 7, kh = (o - 8) >> 3;
            CP_ASYNC16(sbase + kh * B_HALF_BYTES + sB[i], gB[i] + kt + kh * 64);
        }
    };

    // ---- ldmatrix per-lane bases
    const int row_off = lane & 7;
    const int a_kb = lane >> 4;
    const int b_kb = (lane >> 3) & 1;
    uint32_t aoff[4], boff[4];
    #pragma unroll
    for (int mf = 0; mf < 4; mf++)
        aoff[mf] = (uint32_t)((wm * 64 + mf * 16 + row_off + ((lane >> 3) & 1) * 8) * 128);
    #pragma unroll
    for (int p = 0; p < 4; p++)
        boff[p] = (uint32_t)((wn * 64 + p * 16 + ((lane >> 4) & 1) * 8 + row_off) * 128);

    // ---- prefetch bias into registers (bias is an input; prepass never
    //      touches it -> legal BEFORE the dependency wait)
    const int nbase = n0 + wn * 64;
    float bv[8][2];
    #pragma unroll
    for (int nf = 0; nf < 8; nf++) {
        const int cc = nbase + nf * 8 + 2 * tg;
        bv[nf][0] = __ldg(bias + cc);
        bv[nf][1] = __ldg(bias + cc + 1);
    }

    float acc[4][8][4];
    #pragma unroll
    for (int mf = 0; mf < 4; mf++)
        #pragma unroll
        for (int nf = 0; nf < 8; nf++)
            #pragma unroll
            for (int r = 0; r < 4; r++) acc[mf][nf][r] = 0.f;

    // ---- wait for prepass stores (g_Xh/g_Wh) to be visible, then prefill
    asm volatile("griddepcontrol.wait;" ::: "memory");

    #pragma unroll
    for (int o = 0; o < 24; o++) fill_op(smem_b, o, 0);
    CP_COMMIT();

    uint32_t a_frag[2][4][4];
    uint32_t b_frag[2][4][4];

    for (int it = 0; it < NITER; it++) {
        const int s = it & 1;
        const uint32_t stage = smem_b + s * STAGE_BYTES;
        const uint32_t nstage = smem_b + (s ^ 1) * STAGE_BYTES;
        const int knext = (it + 1) * BK;
        const bool do_fill = (it + 1 < NITER);

        CP_WAIT(0);
        __syncthreads();

        // preload ks=0 fragments, interleaved so first MMA's deps land first
        {
            const uint32_t ac = (uint32_t)((a_kb ^ row_off) << 4);
            const uint32_t bc = (uint32_t)((b_kb ^ row_off) << 4);
            LDMATRIX_X4(a_frag[0][0], stage + aoff[0] + ac);
            LDMATRIX_X4(b_frag[0][0], stage + B_BASE_OFF + boff[0] + bc);
            LDMATRIX_X4(a_frag[0][1], stage + aoff[1] + ac);
            LDMATRIX_X4(b_frag[0][1], stage + B_BASE_OFF + boff[1] + bc);
            LDMATRIX_X4(a_frag[0][2], stage + aoff[2] + ac);
            LDMATRIX_X4(b_frag[0][2], stage + B_BASE_OFF + boff[2] + bc);
            LDMATRIX_X4(a_frag[0][3], stage + aoff[3] + ac);
            LDMATRIX_X4(b_frag[0][3], stage + B_BASE_OFF + boff[3] + bc);
        }

        #pragma unroll
        for (int ks = 0; ks < KSTEPS; ks++) {
            const int cur = ks & 1;
            // fill 6 ops/k-step over ks=0..3; commit at ks==3 =>
            // group ages ~4 k-steps (~1300 cyc) before the next wait
            if (do_fill && ks < 4) {
                #pragma unroll
                for (int j = 0; j < 6; j++)
                    fill_op(nstage, ks * 6 + j, knext);
                if (ks == 3) CP_COMMIT();
            }
            if (ks + 1 < KSTEPS) {
                const int nb  = cur ^ 1;
                const int kn  = ks + 1;
                const int kh  = kn >> 2;
                const int kk  = kn & 3;
                const uint32_t abase = stage + kh * A_HALF_BYTES;
                const uint32_t bbase = stage + B_BASE_OFF + kh * B_HALF_BYTES;
                const uint32_t ac = (uint32_t)((((2 * kk) | a_kb) ^ row_off) << 4);
                const uint32_t bc = (uint32_t)((((2 * kk) | b_kb) ^ row_off) << 4);
                #pragma unroll
                for (int mf = 0; mf < 4; mf++) LDMATRIX_X4(a_frag[nb][mf], abase + aoff[mf] + ac);
                #pragma unroll
                for (int p = 0; p < 4; p++)    LDMATRIX_X4(b_frag[nb][p],  bbase + boff[p]  + bc);
            }
            #pragma unroll
            for (int mf = 0; mf < 4; mf++)
                #pragma unroll
                for (int p = 0; p < 4; p++) {
                    mma_f16(acc[mf][2 * p],     a_frag[cur][mf], &b_frag[cur][p][0]);
                    mma_f16(acc[mf][2 * p + 1], a_frag[cur][mf], &b_frag[cur][p][2]);
                }
        }
        if (!do_fill) CP_COMMIT();   // balance group accounting on last iter
    }

    // ---- epilogue: bias + store (bias already in registers)
    const int mbase = m0 + wm * 64;
    #pragma unroll
    for (int nf = 0; nf < 8; nf++) {
        const int cc = nbase + nf * 8 + 2 * tg;
        #pragma unroll
        for (int mf = 0; mf < 4; mf++) {
            const int r = mbase + mf * 16 + gid;
            float2 v0 = make_float2(acc[mf][nf][0] + bv[nf][0], acc[mf][nf][1] + bv[nf][1]);
            float2 v1 = make_float2(acc[mf][nf][2] + bv[nf][0], acc[mf][nf][3] + bv[nf][1]);
            *(float2*)(C + (size_t)r * OUT_F + cc)       = v0;
            *(float2*)(C + (size_t)(r + 8) * OUT_F + cc) = v1;
        }
    }
}

// ---------------------------------------------------------------- launch
extern "C" void kernel_launch(void* const* d_in, const int* in_sizes, int n_in,
                              void* d_out, int out_size) {
    const float* x    = (const float*)d_in[0];   // [4,2048,4096]
    const float* cb   = (const float*)d_in[1];   // [4096,8]
    const void*  idx  = d_in[2];                 // [NBLOCKS] int32 or int64
    const float* bias = (const float*)d_in[3];   // [4096]
    float* out = (float*)d_out;

    k_prepass<<<PRE_GRID, 256>>>((const float4*)x, idx, cb);

    cudaFuncSetAttribute(k_gemm, cudaFuncAttributeMaxDynamicSharedMemorySize, SMEM_TOTAL);

    // PDL: let k_gemm launch while k_prepass drains; k_gemm's prologue
    // (tables + bias prefetch) runs before griddepcontrol.wait.
    cudaLaunchConfig_t cfg = {};
    cfg.gridDim = dim3(OUT_F / BN, MROWS / BM, 1);   // (16, 64)
    cfg.blockDim = dim3(256, 1, 1);
    cfg.dynamicSmemBytes = SMEM_TOTAL;
    cfg.stream = 0;
    cudaLaunchAttribute attr[1];
    attr[0].id = cudaLaunchAttributeProgrammaticStreamSerialization;
    attr[0].val.programmaticStreamSerializationAllowed = 1;
    cfg.attrs = attr;
    cfg.numAttrs = 1;
    cudaLaunchKernelEx(&cfg, k_gemm, bias, out);
}